// round 4
// baseline (speedup 1.0000x reference)
#include <cuda_runtime.h>

#define NQ      14
#define NSTATE  16384
#define THREADS 256

// XOR swizzle: makes scalar LDS/STS conflict-free for all three pass
// orientations (low-bit, mid-bit, high-bit subcubes) and linear sweeps.
__device__ __forceinline__ int swz(int i) { return i ^ ((i >> 5) & 31); }

__global__ __launch_bounds__(THREADS, 3)
void qnn_kernel(const float* __restrict__ x,
                const float* __restrict__ w,
                float* __restrict__ out)
{
    extern __shared__ float st[];          // 16384 floats, swizzled layout
    __shared__ float c0w[NQ], s0w[NQ];     // init angles (x + weights[0]) by wire
    __shared__ float c1w[NQ], s1w[NQ];     // layer-1 angles by wire
    __shared__ float lo[256], hi[64];      // product-state partial tables
    __shared__ float red[NQ];

    const int tid = threadIdx.x;
    const int b   = blockIdx.x;

    if (tid < NQ) {
        float t0 = 0.5f * (x[b * NQ + tid] + w[tid]);        // fused init+layer0 RY
        float t1 = 0.5f * w[NQ + tid];                        // layer-1 RY
        c0w[tid] = cosf(t0); s0w[tid] = sinf(t0);
        c1w[tid] = cosf(t1); s1w[tid] = sinf(t1);
        red[tid] = 0.0f;
    }
    __syncthreads();

    // Partial-product tables over index bits. Wire w <-> bit p = 13-w.
    {
        float p = 1.0f;
        #pragma unroll
        for (int pb = 0; pb < 8; ++pb)
            p *= ((tid >> pb) & 1) ? s0w[13 - pb] : c0w[13 - pb];
        lo[tid] = p;
    }
    if (tid < 64) {
        float p = 1.0f;
        #pragma unroll
        for (int pb = 8; pb < 14; ++pb)
            p *= ((tid >> (pb - 8)) & 1) ? s0w[13 - pb] : c0w[13 - pb];
        hi[tid] = p;
    }
    __syncthreads();

    // Init, with the FIRST CNOT-chain permutation folded in:
    // st[j] = amp_product[ F^{-1}(j) ].
    // Forward map F (CNOT ring): n_p = XOR(bits p..13) for p<=12; n_13 = XOR(bits 0..12).
    // Inverse: b_p = n_p ^ n_{p+1} (p<=11); b_13 = n_0 ^ n_13; b_12 = n_12 ^ n_0 ^ n_13.
    for (int j = tid; j < NSTATE; j += THREADS) {
        int low = (j ^ (j >> 1)) & 0x0FFF;
        int b13 = (j ^ (j >> 13)) & 1;
        int b12 = ((j >> 12) ^ j ^ (j >> 13)) & 1;
        int m   = low | (b12 << 12) | (b13 << 13);
        st[swz(j)] = hi[m >> 8] * lo[m & 255];
    }
    __syncthreads();

    // ---- Layer-1 RY butterflies: bits 0..4 (wires 13..9) ----
    {
        const int lane = tid & 31, hi3 = tid >> 5;
        #pragma unroll
        for (int it = 0; it < 2; ++it) {
            const int base = (((it << 3) | hi3) << 10) | (lane << 5);
            float a[32];
            #pragma unroll
            for (int m = 0; m < 32; ++m) a[m] = st[base | (m ^ lane)];
            #pragma unroll
            for (int q = 0; q < 5; ++q) {
                const float c = c1w[13 - q], s = s1w[13 - q];
                const int str = 1 << q;
                #pragma unroll
                for (int k = 0; k < 32; ++k) if (!(k & str)) {
                    float a0 = a[k], a1 = a[k | str];
                    a[k]       = c * a0 - s * a1;
                    a[k | str] = s * a0 + c * a1;
                }
            }
            #pragma unroll
            for (int m = 0; m < 32; ++m) st[base | (m ^ lane)] = a[m];
        }
    }
    __syncthreads();

    // ---- bits 5..9 (wires 8..4) ----
    {
        const int low5 = tid & 31, hi3 = tid >> 5;
        #pragma unroll
        for (int it = 0; it < 2; ++it) {
            const int top = (((it << 3) | hi3) << 10);
            float a[32];
            #pragma unroll
            for (int m = 0; m < 32; ++m) a[m] = st[top | (m << 5) | (low5 ^ m)];
            #pragma unroll
            for (int q = 0; q < 5; ++q) {
                const float c = c1w[8 - q], s = s1w[8 - q];   // wire 13-(5+q)
                const int str = 1 << q;
                #pragma unroll
                for (int k = 0; k < 32; ++k) if (!(k & str)) {
                    float a0 = a[k], a1 = a[k | str];
                    a[k]       = c * a0 - s * a1;
                    a[k | str] = s * a0 + c * a1;
                }
            }
            #pragma unroll
            for (int m = 0; m < 32; ++m) st[top | (m << 5) | (low5 ^ m)] = a[m];
        }
    }
    __syncthreads();

    // ---- bits 10..13 (wires 3..0) ----
    {
        #pragma unroll
        for (int it = 0; it < 4; ++it) {
            const int low10 = (it << 8) | tid;
            const int sl = low10 ^ ((low10 >> 5) & 31);
            float a[16];
            #pragma unroll
            for (int m = 0; m < 16; ++m) a[m] = st[(m << 10) | sl];
            #pragma unroll
            for (int q = 0; q < 4; ++q) {
                const float c = c1w[3 - q], s = s1w[3 - q];   // wire 13-(10+q)
                const int str = 1 << q;
                #pragma unroll
                for (int k = 0; k < 16; ++k) if (!(k & str)) {
                    float a0 = a[k], a1 = a[k | str];
                    a[k]       = c * a0 - s * a1;
                    a[k | str] = s * a0 + c * a1;
                }
            }
            #pragma unroll
            for (int m = 0; m < 16; ++m) st[(m << 10) | sl] = a[m];
        }
    }
    __syncthreads();

    // Expectation pass with the SECOND CNOT chain folded into the signs:
    // <Z_w> = sum_j st[j]^2 * (1 - 2 * bit_{13-w}(F(j))).
    // Suffix-parity scan: bit p of y = XOR(bits p..13 of j).
    float acc[NQ];
    #pragma unroll
    for (int q = 0; q < NQ; ++q) acc[q] = 0.0f;

    for (int j = tid; j < NSTATE; j += THREADS) {
        float v = st[swz(j)];
        float p2 = v * v;
        int y = j;
        y ^= y >> 1; y ^= y >> 2; y ^= y >> 4; y ^= y >> 8;
        // wire 0 (p=13): parity of bits 0..12 = total_parity ^ bit13
        acc[0] += ((y ^ (j >> 13)) & 1) ? -p2 : p2;
        #pragma unroll
        for (int wq = 1; wq < NQ; ++wq)
            acc[wq] += ((y >> (13 - wq)) & 1) ? -p2 : p2;
    }

    // Reduce: warp shuffle, then shared atomics across the 8 warps.
    #pragma unroll
    for (int wq = 0; wq < NQ; ++wq) {
        float v = acc[wq];
        #pragma unroll
        for (int o = 16; o > 0; o >>= 1)
            v += __shfl_xor_sync(0xffffffffu, v, o);
        if ((tid & 31) == 0) atomicAdd(&red[wq], v);
    }
    __syncthreads();

    if (tid < NQ) out[b * NQ + tid] = red[tid];
}

extern "C" void kernel_launch(void* const* d_in, const int* in_sizes, int n_in,
                              void* d_out, int out_size)
{
    const float* x = (const float*)d_in[0];   // (512, 14) fp32
    const float* w = (const float*)d_in[1];   // (2, 14)  fp32
    float* out = (float*)d_out;               // (512, 14) fp32

    const int B = in_sizes[0] / NQ;

    cudaFuncSetAttribute(qnn_kernel,
                         cudaFuncAttributeMaxDynamicSharedMemorySize,
                         NSTATE * (int)sizeof(float));
    qnn_kernel<<<B, THREADS, NSTATE * sizeof(float)>>>(x, w, out);
}

// round 5
// speedup vs baseline: 2.0013x; 2.0013x over previous
#include <cuda_runtime.h>

#define NQ      14
#define NSTATE  16384
#define THREADS 256

__global__ __launch_bounds__(THREADS, 3)
void qnn_kernel(const float* __restrict__ x,
                const float* __restrict__ wts,
                float* __restrict__ out)
{
    extern __shared__ float st[];          // 16384 floats, swizzled: st[j ^ ((j>>5)&31)]
    __shared__ float c0w[NQ], s0w[NQ];     // fused init+layer0 angles
    __shared__ float c1w[NQ], s1w[NQ];     // layer-1 angles
    __shared__ float lo[256];              // product table, bits 0..7 of basis index
    __shared__ float hi[64];               // product table, bits 8..13
    __shared__ float red[NQ];

    const int tid  = threadIdx.x;
    const int b    = blockIdx.x;
    const int lane = tid & 31;
    const int hi3  = tid >> 5;

    if (tid < NQ) {
        float t0 = 0.5f * (x[b * NQ + tid] + wts[tid]);
        float t1 = 0.5f * wts[NQ + tid];
        c0w[tid] = cosf(t0); s0w[tid] = sinf(t0);
        c1w[tid] = cosf(t1); s1w[tid] = sinf(t1);
        red[tid] = 0.0f;
    }
    __syncthreads();

    // Partial-product tables (wire w <-> bit p = 13-w of the basis index).
    {
        float p = 1.0f;
        #pragma unroll
        for (int pb = 0; pb < 8; ++pb)
            p *= ((tid >> pb) & 1) ? s0w[13 - pb] : c0w[13 - pb];
        lo[tid] = p;
    }
    if (tid < 64) {
        float p = 1.0f;
        #pragma unroll
        for (int pb = 8; pb < 14; ++pb)
            p *= ((tid >> (pb - 8)) & 1) ? s0w[13 - pb] : c0w[13 - pb];
        hi[tid] = p;
    }
    __syncthreads();

    // ================= Pass A: fused init-gather + RY butterflies on bits 0..4 =================
    // st[swz(j)] = hi[(F^-1(j))>>8] * lo[(F^-1(j))&255] then butterfly wires 13..9.
    // With j = ((it<<3|hi3)<<10) | (lane<<5) | mm:
    //   hi index = K0 ^ (it*0x30) ^ (mm0*0x30)  -> only TWO distinct hi values per thread.
    //   lo index = Ct ^ (mm ^ (mm>>1))          -> Ct loop-invariant, gray(mm) compile-time.
    {
        const int l0 = lane & 1, l3 = (lane >> 3) & 1, l4 = (lane >> 4) & 1;
        const int h0 = hi3 & 1, h1 = (hi3 >> 1) & 1, h2 = (hi3 >> 2) & 1;
        const int K0 = (l3 ^ l4) | ((l4 ^ h0) << 1) | ((h0 ^ h1) << 2)
                     | ((h1 ^ h2) << 3) | (h2 << 4);
        const float hvA0 = hi[K0];
        const float hvB0 = hi[K0 ^ 0x30];
        const int Ct = (l0 << 4) | (((lane ^ (lane >> 1)) & 7) << 5);

        #pragma unroll
        for (int it = 0; it < 2; ++it) {
            const int base = (((it << 3) | hi3) << 10) | (lane << 5);
            const float hvEven = it ? hvB0 : hvA0;   // mm bit0 = 0
            const float hvOdd  = it ? hvA0 : hvB0;   // mm bit0 = 1
            float a[32];
            #pragma unroll
            for (int mm = 0; mm < 32; ++mm) {
                const int g = mm ^ (mm >> 1);        // compile-time
                a[mm] = ((mm & 1) ? hvOdd : hvEven) * lo[Ct ^ g];
            }
            #pragma unroll
            for (int q = 0; q < 5; ++q) {
                const float c = c1w[13 - q], s = s1w[13 - q];
                const int str = 1 << q;
                #pragma unroll
                for (int k = 0; k < 32; ++k) if (!(k & str)) {
                    float a0 = a[k], a1 = a[k | str];
                    a[k]       = c * a0 - s * a1;
                    a[k | str] = s * a0 + c * a1;
                }
            }
            #pragma unroll
            for (int mm = 0; mm < 32; ++mm) st[base | (mm ^ lane)] = a[mm];
        }
    }
    __syncthreads();

    // ================= Pass B: RY butterflies on bits 5..9 (wires 8..4) =================
    {
        #pragma unroll
        for (int it = 0; it < 2; ++it) {
            const int top = (((it << 3) | hi3) << 10);
            float a[32];
            #pragma unroll
            for (int m = 0; m < 32; ++m) a[m] = st[top | (m << 5) | (lane ^ m)];
            #pragma unroll
            for (int q = 0; q < 5; ++q) {
                const float c = c1w[8 - q], s = s1w[8 - q];
                const int str = 1 << q;
                #pragma unroll
                for (int k = 0; k < 32; ++k) if (!(k & str)) {
                    float a0 = a[k], a1 = a[k | str];
                    a[k]       = c * a0 - s * a1;
                    a[k | str] = s * a0 + c * a1;
                }
            }
            #pragma unroll
            for (int m = 0; m < 32; ++m) st[top | (m << 5) | (lane ^ m)] = a[m];
        }
    }
    __syncthreads();

    // ====== Pass C: butterflies on bits 10..13 (wires 3..0) fused with measurement ======
    // j = (m<<10) | (it<<8) | tid. Sign of wire w = suffix-parity bit of F(j):
    //   w=0: par(tid)^it0^it1 ^ par(m&7)      w=1: par(m>>2)   w=2: par(m>>1)  w=3: par(m)
    //   w=4: it1 ^ par(m)                     w=5: (it0^it1) ^ par(m)
    //   w=6..13 (p=7..0): partid(p) ^ (it0^it1) ^ par(m)
    // All m/it sign patterns are compile-time; tid parities applied once at the end.
    float TA_pm = 0.f, TA4 = 0.f, TA3 = 0.f, TB = 0.f, TW1 = 0.f, TW2 = 0.f;
    const int tbase = tid ^ ((tid >> 5) & 7);

    #pragma unroll
    for (int it = 0; it < 4; ++it) {
        const int sl = (it << 8) | (tbase ^ (it << 3));
        float a[16];
        #pragma unroll
        for (int m = 0; m < 16; ++m) a[m] = st[(m << 10) | sl];
        #pragma unroll
        for (int q = 0; q < 4; ++q) {
            const float c = c1w[3 - q], s = s1w[3 - q];
            const int str = 1 << q;
            #pragma unroll
            for (int k = 0; k < 16; ++k) if (!(k & str)) {
                float a0 = a[k], a1 = a[k | str];
                a[k]       = c * a0 - s * a1;
                a[k | str] = s * a0 + c * a1;
            }
        }
        float p2[16];
        #pragma unroll
        for (int m = 0; m < 16; ++m) p2[m] = a[m] * a[m];

        // Hadamard tree over m for the 4 distinct m-sign patterns.
        float u0[8], u1[8];
        #pragma unroll
        for (int m = 0; m < 8; ++m) { u0[m] = p2[m] + p2[m | 8]; u1[m] = p2[m] - p2[m | 8]; }
        float w1_[4], z1[4];
        #pragma unroll
        for (int m = 0; m < 4; ++m) { w1_[m] = u1[m] - u1[m | 4]; z1[m] = u0[m] - u0[m | 4]; }
        const float A   = w1_[0] - w1_[1] - w1_[2] + w1_[3];   // (-1)^par(m)
        const float Bv  = z1[0]  - z1[1]  - z1[2]  + z1[3];    // (-1)^par(m&7)
        const float W1v = w1_[0] + w1_[1] + w1_[2] + w1_[3];   // (-1)^(m2^m3)
        const float W2v = w1_[0] + w1_[1] - w1_[2] - w1_[3];   // (-1)^(m1^m2^m3)

        // it-sign folds (compile-time): sgn_pm = (-1)^(it0^it1); sgn_4 = (-1)^(it>>1)
        const float sgn_pm = (it == 0 || it == 3) ? 1.f : -1.f;
        const float sgn_4  = (it < 2) ? 1.f : -1.f;
        TA_pm += sgn_pm * A;
        TA4   += sgn_4  * A;
        TA3   += A;
        TB    += sgn_pm * Bv;
        TW1   += W1v;
        TW2   += W2v;
    }

    // Per-thread tid suffix parities: bit p of y = XOR(tid bits p..7).
    int y = tid; y ^= y >> 4; y ^= y >> 2; y ^= y >> 1;

    float vals[NQ];
    vals[0] = (y & 1) ? -TB : TB;       // par8(tid)
    vals[1] = TW1;
    vals[2] = TW2;
    vals[3] = TA3;
    vals[4] = TA4;
    vals[5] = TA_pm;
    #pragma unroll
    for (int ww = 6; ww < NQ; ++ww) {
        const int p = 13 - ww;          // 7..0
        vals[ww] = ((y >> p) & 1) ? -TA_pm : TA_pm;
    }

    #pragma unroll
    for (int ww = 0; ww < NQ; ++ww) {
        float v = vals[ww];
        #pragma unroll
        for (int o = 16; o > 0; o >>= 1)
            v += __shfl_xor_sync(0xffffffffu, v, o);
        if (lane == 0) atomicAdd(&red[ww], v);
    }
    __syncthreads();

    if (tid < NQ) out[b * NQ + tid] = red[tid];
}

extern "C" void kernel_launch(void* const* d_in, const int* in_sizes, int n_in,
                              void* d_out, int out_size)
{
    const float* x = (const float*)d_in[0];   // (512, 14) fp32
    const float* w = (const float*)d_in[1];   // (2, 14)  fp32
    float* out = (float*)d_out;               // (512, 14) fp32

    const int B = in_sizes[0] / NQ;

    cudaFuncSetAttribute(qnn_kernel,
                         cudaFuncAttributeMaxDynamicSharedMemorySize,
                         NSTATE * (int)sizeof(float));
    qnn_kernel<<<B, THREADS, NSTATE * sizeof(float)>>>(x, w, out);
}

// round 6
// speedup vs baseline: 5.5560x; 2.7762x over previous
#include <cuda_runtime.h>

#define NQ 14

// Transfer-matrix contraction of the 14-qubit, 2-layer RY+CNOT-ring circuit.
// One thread = one batch element, all 14 expectations in closed form.
//
// rho[b0][b0'] is a 4-vector over (P,P') = (prefix parity of j, of j'),
// index P*2+P'. Per site w=1..13:
//   mix P, mix P' with (c,s)=(cos a_w, sin a_w), then elementwise
//   K_w = [[ct,-st],[-st,-ct]] (ct=cos th_w, st=sin th_w).
__global__ __launch_bounds__(128)
void qnn_tm_kernel(const float* __restrict__ x,
                   const float* __restrict__ wt,
                   float* __restrict__ out, int B)
{
    int b = blockIdx.x * blockDim.x + threadIdx.x;
    if (b >= B) return;

    float ca[NQ], sa[NQ], ctt[NQ], stt[NQ], c2[NQ], s2[NQ];
    #pragma unroll
    for (int q = 0; q < NQ; ++q) {
        float alpha = 0.5f * (x[b * NQ + q] + wt[q]);
        __sincosf(alpha, &sa[q], &ca[q]);
        __sincosf(wt[NQ + q], &stt[q], &ctt[q]);
        c2[q] = ca[q] * ca[q] - sa[q] * sa[q];   // cos(2a)
        s2[q] = 2.0f * ca[q] * sa[q];            // sin(2a)
    }

    // Suffix products Cgt[w] = prod_{k=w+1..13} cos(2a_k)
    float Cgt[NQ];
    Cgt[NQ - 1] = 1.0f;
    #pragma unroll
    for (int q = NQ - 2; q >= 1; --q) Cgt[q] = Cgt[q + 1] * c2[q + 1];

    const float ct0 = ctt[0], st0 = stt[0];

    // Branch vectors: boundary qubit-0 bits (b0, b0').
    float r00[4] = { ca[0] * ca[0], 0.f, 0.f, 0.f };
    float r01[4] = { 0.f, ca[0] * sa[0], 0.f, 0.f };
    float r10[4] = { 0.f, 0.f, ca[0] * sa[0], 0.f };
    float r11[4] = { 0.f, 0.f, 0.f, sa[0] * sa[0] };

    float E[NQ];

    #pragma unroll
    for (int w = 1; w < NQ; ++w) {
        const float c = ca[w], s = sa[w], ct = ctt[w], st = stt[w];

        #define STEP(r) {                                   \
            float t0 = c * r[0] + s * r[2];                 \
            float t1 = c * r[1] + s * r[3];                 \
            float t2 = c * r[2] + s * r[0];                 \
            float t3 = c * r[3] + s * r[1];                 \
            float u0 = c * t0 + s * t1;                     \
            float u1 = c * t1 + s * t0;                     \
            float u2 = c * t2 + s * t3;                     \
            float u3 = c * t3 + s * t2;                     \
            r[0] =  ct * u0; r[1] = -st * u1;               \
            r[2] = -st * u2; r[3] = -ct * u3; }

        STEP(r00) STEP(r01) STEP(r10) STEP(r11)
        #undef STEP

        if (w <= NQ - 2) {
            // Backward factor: diag part scaled by suffix cos(2a) product,
            // off-diag part carries sin(2a_{w+1}); S vanishes on equal
            // branches, D vanishes on unequal ones.
            float dA = (r00[0] - r00[3]) - (r11[0] - r11[3]);
            float sB = (r01[0] + r01[3]) + (r10[0] + r10[3]);
            float oB = (r01[1] + r01[2]) + (r10[1] + r10[2]);
            E[w] = ct0 * Cgt[w] * dA - st0 * (sB + s2[w + 1] * oB);
        }
    }

    // Wire 0: T_0 = {1..13}; site-0 operator is identity -> delta on
    // (P_13 ^ b0, P'_13 ^ b0'): diagonal of equal branches + off-diagonal
    // of unequal branches.
    E[0] = (r00[0] + r00[3] + r11[0] + r11[3])
         + (r01[1] + r01[2] + r10[1] + r10[2]);

    // Wire 13: all sites carry K; contract directly with K_0 shifted by the
    // boundary bits of each branch.
    E[NQ - 1] = ct0 * ((r00[0] - r00[3]) - (r11[0] - r11[3]))
              - st0 * (r00[1] + r00[2] + r11[1] + r11[2])
              - st0 * (r01[0] + r01[3] + r10[0] + r10[3])
              + ct0 * ((r01[1] - r01[2]) - (r10[1] - r10[2]));

    #pragma unroll
    for (int q = 0; q < NQ; ++q) out[b * NQ + q] = E[q];
}

extern "C" void kernel_launch(void* const* d_in, const int* in_sizes, int n_in,
                              void* d_out, int out_size)
{
    const float* x  = (const float*)d_in[0];   // (B, 14) fp32
    const float* wt = (const float*)d_in[1];   // (2, 14) fp32
    float* out = (float*)d_out;                // (B, 14) fp32

    const int B = in_sizes[0] / NQ;
    const int threads = 128;
    qnn_tm_kernel<<<(B + threads - 1) / threads, threads>>>(x, wt, out, B);
}

// round 10
// speedup vs baseline: 7.8520x; 1.4133x over previous
#include <cuda_runtime.h>

#define NQ   14
#define EPB  32          // batch elements per block
#define TPB  128         // 4 threads (branches) per element

// Transfer-matrix contraction of the 14-qubit 2-layer RY+CNOT-ring circuit.
// 4 threads per batch element, one per boundary branch of qubit 0; readout
// weights are folded per-branch so the final combine is a plain 4-way sum.
__global__ __launch_bounds__(TPB)
void qnn_tm4_kernel(const float* __restrict__ x,
                    const float* __restrict__ wt,
                    float* __restrict__ out, int B)
{
    __shared__ float sx[EPB * NQ];                 // staged x
    __shared__ float sw0[NQ], swc[NQ], sws[NQ];    // W0 raw; cos/sin of W1
    __shared__ float sca[EPB][NQ], ssa[EPB][NQ];   // cos/sin alpha
    __shared__ float sc2[EPB][NQ], ss2[EPB][NQ];   // cos/sin 2*alpha
    __shared__ float cont[TPB][NQ];                // per-branch weighted contribs

    const int tid  = threadIdx.x;
    const int base = blockIdx.x * EPB;

    // ---- phase 0: coalesced stage of x + weight trig ----
    #pragma unroll
    for (int i = tid; i < EPB * NQ; i += TPB) {
        int g = base * NQ + i;
        sx[i] = (g < B * NQ) ? x[g] : 0.0f;
    }
    if (tid < NQ) {
        sw0[tid] = wt[tid];
        float s, c;
        __sincosf(wt[NQ + tid], &s, &c);
        swc[tid] = c; sws[tid] = s;
    }
    __syncthreads();

    const int e  = tid >> 2;
    const int br = tid & 3;

    // ---- per-element alpha trig, split 4 ways across the element's lanes ----
    for (int q = br; q < NQ; q += 4) {
        float a = 0.5f * (sx[e * NQ + q] + sw0[q]);
        float s, c;
        __sincosf(a, &s, &c);
        sca[e][q] = c;  ssa[e][q] = s;
        sc2[e][q] = c * c - s * s;
        ss2[e][q] = 2.0f * c * s;
    }
    __syncthreads();

    const bool  diag  = (br == 0) || (br == 3);
    const float sgn_d = (br == 0) ? 1.0f : -1.0f;
    const float ct0 = swc[0], st0 = sws[0];

    // Diag lanes need the suffix products Cgt[w] = prod_{k>w} cos(2a_k);
    // compute privately in registers (12 FMUL) — no cross-thread dependency.
    float cg[NQ];
    if (diag) {
        float p = 1.0f;
        cg[NQ - 1] = 1.0f;
        #pragma unroll
        for (int q = NQ - 2; q >= 1; --q) { p *= sc2[e][q + 1]; cg[q] = p; }
    }

    // ---- phase 1: one branch chain per thread, weights folded in ----
    const float c0 = sca[e][0], s0 = ssa[e][0];
    float r0 = (br == 0) ? c0 * c0 : 0.0f;
    float r1 = (br == 1) ? c0 * s0 : 0.0f;
    float r2 = (br == 2) ? c0 * s0 : 0.0f;
    float r3 = (br == 3) ? s0 * s0 : 0.0f;

    #pragma unroll
    for (int w = 1; w < NQ; ++w) {
        const float c  = sca[e][w], s  = ssa[e][w];
        const float ct = swc[w],    st = sws[w];
        float t0 = c * r0 + s * r2, t1 = c * r1 + s * r3;
        float t2 = c * r2 + s * r0, t3 = c * r3 + s * r1;
        float u0 = c * t0 + s * t1, u1 = c * t1 + s * t0;
        float u2 = c * t2 + s * t3, u3 = c * t3 + s * t2;
        r0 =  ct * u0; r1 = -st * u1; r2 = -st * u2; r3 = -ct * u3;
        if (w <= NQ - 2) {
            // diag (br0/3): +-(r0-r3) * ct0 * Cgt[w]
            // off  (br1/2): -st0 * ( (r0+r3) + sin(2a_{w+1})*(r1+r2) )
            cont[tid][w] = diag
                ? (sgn_d * ct0) * cg[w] * (r0 - r3)
                : -st0 * ((r0 + r3) + ss2[e][w + 1] * (r1 + r2));
        }
    }
    {
        float v13;
        if (br == 0)      v13 =  ct0 * (r0 - r3) - st0 * (r1 + r2);
        else if (br == 3) v13 = -ct0 * (r0 - r3) - st0 * (r1 + r2);
        else if (br == 1) v13 = -st0 * (r0 + r3) + ct0 * (r1 - r2);
        else              v13 = -st0 * (r0 + r3) - ct0 * (r1 - r2);
        cont[tid][NQ - 1] = v13;                       // wire 13
        cont[tid][0] = diag ? (r0 + r3) : (r1 + r2);   // wire 0 (identity op)
    }
    __syncthreads();

    // ---- phase 2: branch-free 4-way sum, coalesced store ----
    for (int i = tid; i < EPB * NQ; i += TPB) {
        int ee = i / NQ, w = i - ee * NQ;
        int t4 = ee << 2;
        float Ev = (cont[t4][w] + cont[t4 + 1][w])
                 + (cont[t4 + 2][w] + cont[t4 + 3][w]);
        int g = (base + ee) * NQ + w;
        if (g < B * NQ) out[g] = Ev;
    }
}

extern "C" void kernel_launch(void* const* d_in, const int* in_sizes, int n_in,
                              void* d_out, int out_size)
{
    const float* x  = (const float*)d_in[0];   // (B, 14) fp32
    const float* wt = (const float*)d_in[1];   // (2, 14) fp32
    float* out = (float*)d_out;                // (B, 14) fp32

    const int B = in_sizes[0] / NQ;
    qnn_tm4_kernel<<<(B + EPB - 1) / EPB, TPB>>>(x, wt, out, B);
}

// round 11
// speedup vs baseline: 7.9330x; 1.0103x over previous
#include <cuda_runtime.h>

#define NQ   14
#define EPB  32          // batch elements per block
#define TPB  128         // 4 lanes (branches) per element, quad-local comms only

// Transfer-matrix contraction of the 14-qubit 2-layer RY+CNOT-ring circuit.
// 4 lanes per batch element (one per boundary branch of qubit 0). All
// cross-lane exchange is width-4 warp shuffles: no shared memory, no barriers.
__global__ __launch_bounds__(TPB)
void qnn_warp_kernel(const float* __restrict__ x,
                     const float* __restrict__ wt,
                     float* __restrict__ out, int B)
{
    const int tid  = threadIdx.x;
    const int e    = blockIdx.x * EPB + (tid >> 2);
    const int br   = tid & 3;
    const bool live = (e < B);

    // ---- each lane computes trig for sites q = 4i + br (alpha AND weights) ----
    float axc[4], axs[4], wtc[4], wtsn[4];
    #pragma unroll
    for (int i = 0; i < 4; ++i) {
        const int q = 4 * i + br;
        float a = 0.0f, ww = 0.0f;
        if (q < NQ) {
            ww = __ldg(&wt[NQ + q]);
            if (live) a = 0.5f * (__ldg(&x[e * NQ + q]) + __ldg(&wt[q]));
        }
        __sincosf(a,  &axs[i],  &axc[i]);
        __sincosf(ww, &wtsn[i], &wtc[i]);
    }

    // ---- quad-shuffle gather: all 14 sites' coefficients into registers ----
    float ca[NQ], sa[NQ], cw[NQ], sw[NQ];
    #pragma unroll
    for (int w = 0; w < NQ; ++w) {
        const int i = w >> 2, l = w & 3;
        ca[w] = __shfl_sync(0xffffffffu, axc[i],  l, 4);
        sa[w] = __shfl_sync(0xffffffffu, axs[i],  l, 4);
        cw[w] = __shfl_sync(0xffffffffu, wtc[i],  l, 4);
        sw[w] = __shfl_sync(0xffffffffu, wtsn[i], l, 4);
    }

    // Local doubles: c2 = cos(2a), s2 = sin(2a); suffix products cg[w] = prod_{k>w} c2[k]
    float s2[NQ], cg[NQ];
    #pragma unroll
    for (int w = 0; w < NQ; ++w) s2[w] = 2.0f * ca[w] * sa[w];
    {
        float p = 1.0f;
        cg[NQ - 1] = 1.0f;
        #pragma unroll
        for (int q = NQ - 2; q >= 1; --q) {
            p *= ca[q + 1] * ca[q + 1] - sa[q + 1] * sa[q + 1];
            cg[q] = p;
        }
    }

    const bool  diag  = (br == 0) || (br == 3);
    const float sgn_d = (br == 0) ? 1.0f : -1.0f;
    const float ct0 = cw[0], st0 = sw[0];

    // ---- branch chain (identical math to the verified R10 kernel) ----
    const float c0 = ca[0], s0 = sa[0];
    float r0 = (br == 0) ? c0 * c0 : 0.0f;
    float r1 = (br == 1) ? c0 * s0 : 0.0f;
    float r2 = (br == 2) ? c0 * s0 : 0.0f;
    float r3 = (br == 3) ? s0 * s0 : 0.0f;

    float Ev[NQ];

    #pragma unroll
    for (int w = 1; w < NQ; ++w) {
        const float c  = ca[w], s  = sa[w];
        const float ct = cw[w], st = sw[w];
        float t0 = c * r0 + s * r2, t1 = c * r1 + s * r3;
        float t2 = c * r2 + s * r0, t3 = c * r3 + s * r1;
        float u0 = c * t0 + s * t1, u1 = c * t1 + s * t0;
        float u2 = c * t2 + s * t3, u3 = c * t3 + s * t2;
        r0 =  ct * u0; r1 = -st * u1; r2 = -st * u2; r3 = -ct * u3;
        if (w <= NQ - 2) {
            Ev[w] = diag
                ? (sgn_d * ct0) * cg[w] * (r0 - r3)
                : -st0 * ((r0 + r3) + s2[w + 1] * (r1 + r2));
        }
    }
    {
        float v13;
        if (br == 0)      v13 =  ct0 * (r0 - r3) - st0 * (r1 + r2);
        else if (br == 3) v13 = -ct0 * (r0 - r3) - st0 * (r1 + r2);
        else if (br == 1) v13 = -st0 * (r0 + r3) + ct0 * (r1 - r2);
        else              v13 = -st0 * (r0 + r3) - ct0 * (r1 - r2);
        Ev[NQ - 1] = v13;                        // wire 13
        Ev[0] = diag ? (r0 + r3) : (r1 + r2);    // wire 0 (identity site op)
    }

    // ---- 4-way branch sum via quad butterflies; coalesced quad store ----
    #pragma unroll
    for (int w = 0; w < NQ; ++w) {
        float v = Ev[w];
        v += __shfl_xor_sync(0xffffffffu, v, 1, 4);
        v += __shfl_xor_sync(0xffffffffu, v, 2, 4);
        Ev[w] = v;
    }
    if (live) {
        #pragma unroll
        for (int i = 0; i < 4; ++i) {
            const int q = 4 * i + br;
            if (q < NQ) out[e * NQ + q] = Ev[q];
        }
    }
}

extern "C" void kernel_launch(void* const* d_in, const int* in_sizes, int n_in,
                              void* d_out, int out_size)
{
    const float* x  = (const float*)d_in[0];   // (B, 14) fp32
    const float* wt = (const float*)d_in[1];   // (2, 14) fp32
    float* out = (float*)d_out;                // (B, 14) fp32

    const int B = in_sizes[0] / NQ;
    qnn_warp_kernel<<<(B + EPB - 1) / EPB, TPB>>>(x, wt, out, B);
}